// round 11
// baseline (speedup 1.0000x reference)
#include <cuda_runtime.h>
#include <cstdint>
#include <cstddef>

// Fixed problem shapes
#define MROWS  8192           // B*S
#define INDIM  4096
#define OUTDIM 4096
#define RANK   8
#define NTHR   256            // 8 warps per CTA, 2 CTAs per SM
#define TROWS  32             // rows per tile (lane = row)
#define NTILE  (MROWS/TROWS)  // 256
#define ICH    128            // i-chunk size
#define NCH    (INDIM/ICH)    // 32
#define NBUF   5              // pipeline depth (4 chunks in flight)
#define XSTR   132            // padded row stride in smem floats (conflict-free)
#define XBUF   (TROWS*XSTR)   // 4224 floats per x buffer
#define CHBYTES (TROWS*ICH*4) // 16384 bytes per x chunk

// smem layout (float offsets)
#define S_X    0                              // 5 x 4224 = 21120
#define S_RED  (NBUF*XBUF)                    // 21120: 8 warps x 32 rows x 8
#define S_INT  (S_RED + 8*TROWS*RANK)         // 23168: 32 x 8
#define S_MBAR (S_INT + TROWS*RANK)           // 23424 (8B-aligned: even)
#define S_TOT  (S_MBAR + 2*NBUF + 2)          // 23436 floats
#define SMEM_BYTES (S_TOT*4)                  // 93744 B (2 CTAs = 187.5 KB/SM)

__constant__ float c_nf4[16] = {
    -1.0f, -0.6961928009986877f, -0.5250730514526367f, -0.39491748809814453f,
    -0.28444138169288635f, -0.18477343022823334f, -0.09105003625154495f, 0.0f,
    0.07958029955625534f, 0.16093020141124725f, 0.24611230194568634f,
    0.33791524171829224f, 0.44070982933044434f, 0.5626170039176941f,
    0.7229568362236328f, 1.0f};

// Pre-dequantized weights (scratch __device__ globals; L2-resident, 128 KB each)
__device__ __align__(16) float g_WA[RANK * INDIM];    // [r][i]
__device__ __align__(16) float g_WBt[RANK * OUTDIM];  // [r][o], pre-scaled by 4.0

// Single merged dequant kernel (one launch)
__global__ void dequant_kernel(const int* __restrict__ codesA,
                               const float* __restrict__ absmaxA,
                               const int* __restrict__ codesB,
                               const float* __restrict__ absmaxB) {
    int i = blockIdx.x * blockDim.x + threadIdx.x;
    if (i < RANK * INDIM) {
        g_WA[i] = c_nf4[codesA[i] & 15] * absmaxA[i >> 6];
    } else {
        int j = i - RANK * INDIM;
        if (j < OUTDIM * RANK) {
            int o = j >> 3, r = j & 7;
            g_WBt[r * OUTDIM + o] = 4.0f * c_nf4[codesB[j] & 15] * absmaxB[j >> 6];
        }
    }
}

__device__ __forceinline__ void fma2(unsigned long long& d,
                                     unsigned long long a, unsigned long long b) {
    asm("fma.rn.f32x2 %0, %1, %2, %0;" : "+l"(d) : "l"(a), "l"(b));
}
__device__ __forceinline__ unsigned long long pk2(float v) {
    unsigned long long r; asm("mov.b64 %0, {%1, %1};" : "=l"(r) : "f"(v)); return r;
}
__device__ __forceinline__ unsigned long long pkab(float a, float b) {
    unsigned long long r; asm("mov.b64 %0, {%1, %2};" : "=l"(r) : "f"(a), "f"(b)); return r;
}
__device__ __forceinline__ float2 unpk(unsigned long long v) {
    float2 f; asm("mov.b64 {%0, %1}, %2;" : "=f"(f.x), "=f"(f.y) : "l"(v)); return f;
}

__device__ __forceinline__ void mbar_init(uint32_t a, uint32_t cnt) {
    asm volatile("mbarrier.init.shared.b64 [%0], %1;" :: "r"(a), "r"(cnt) : "memory");
}
__device__ __forceinline__ void mbar_expect_tx(uint32_t a, uint32_t bytes) {
    asm volatile("mbarrier.arrive.expect_tx.shared.b64 _, [%0], %1;"
                 :: "r"(a), "r"(bytes) : "memory");
}
__device__ __forceinline__ void mbar_wait(uint32_t a, uint32_t ph) {
    asm volatile(
        "{\n\t.reg .pred P;\n"
        "W%=:\n\t"
        "mbarrier.try_wait.parity.acquire.cta.shared::cta.b64 P, [%0], %1, 0x989680;\n\t"
        "@P bra.uni D%=;\n\t"
        "bra.uni W%=;\n\t"
        "D%=:\n\t}"
        :: "r"(a), "r"(ph) : "memory");
}
// 1D bulk async copy global->shared with complete_tx on mbar (SASS: UBLKCP)
__device__ __forceinline__ void bulk_ld(uint32_t dst, const void* src,
                                        uint32_t bytes, uint32_t mbar) {
    asm volatile(
        "cp.async.bulk.shared::cluster.global.mbarrier::complete_tx::bytes "
        "[%0], [%1], %2, [%3];"
        :: "r"(dst), "l"(src), "r"(bytes), "r"(mbar) : "memory");
}

// Producer (warp 0 only): 32 bulk ops of 512B, one per tile row.
__device__ __forceinline__ void produce(uint32_t smb, const float* __restrict__ x,
                                        int t0, int grid, int L, int buf, int lane) {
    int tile = t0 + (L >> 5) * grid;
    if (tile >= NTILE) return;
    int ch = L & 31;
    uint32_t mb = smb + (uint32_t)((S_MBAR + 2 * buf) * 4);
    if (lane == 0) mbar_expect_tx(mb, CHBYTES);
    __syncwarp();
    const float* src = x + (size_t)tile * TROWS * INDIM + (size_t)ch * ICH
                         + (size_t)lane * INDIM;
    bulk_ld(smb + (uint32_t)((S_X + buf * XBUF + lane * XSTR) * 4),
            src, ICH * 4, mb);
}

__global__ void __launch_bounds__(NTHR, 2)
qlora_kernel(const float* __restrict__ x, float* __restrict__ out)
{
    extern __shared__ float sm[];
    const int tid = threadIdx.x, lane = tid & 31, wid = tid >> 5;
    const int grid = gridDim.x;
    const int t0 = blockIdx.x;
    if (t0 >= NTILE) return;               // surplus CTAs exit immediately

    uint32_t smb = (uint32_t)__cvta_generic_to_shared(sm);

    if (tid == 0) {
        #pragma unroll
        for (int b = 0; b < NBUF; b++)
            mbar_init(smb + (uint32_t)((S_MBAR + 2 * b) * 4), 1);
    }
    __syncthreads();

    // prologue: issue chunks 0..3 into buffers 0..3
    if (wid == 0) {
        #pragma unroll
        for (int L = 0; L < NBUF - 1; L++)
            produce(smb, x, t0, grid, L, L, lane);
    }

    int pL = NBUF - 1, pbuf = NBUF - 1;    // producer cursor
    int cbuf = 0, cph = 0;                 // consumer cursor (buffer, parity)

    for (int t = t0; t < NTILE; t += grid) {
        unsigned long long a01[RANK], a23[RANK];
        #pragma unroll
        for (int r = 0; r < RANK; r++) { a01[r] = 0ull; a23[r] = 0ull; }

        #pragma unroll 1
        for (int c = 0; c < NCH; c++) {
            mbar_wait(smb + (uint32_t)((S_MBAR + 2 * cbuf) * 4), cph);
            __syncthreads();   // all warps past chunk q-1 (its buffer is reused next)

            if (wid == 0)
                produce(smb, x, t0, grid, pL, pbuf, lane);
            pL++; pbuf = (pbuf + 1 == NBUF) ? 0 : pbuf + 1;

            // consume: lane = row; warp w covers i in [w*16, w*16+16)
            const ulonglong2* xp =
                (const ulonglong2*)(sm + S_X + cbuf * XBUF + lane * XSTR) + wid * 4;
            const ulonglong2* __restrict__ wp =
                (const ulonglong2*)(g_WA + c * ICH) + wid * 4;   // uniform (L1/L2)
            #pragma unroll
            for (int j = 0; j < 4; j++) {
                ulonglong2 xv = xp[j];                 // conflict-free LDS.128
                ulonglong2 wv[RANK];
                #pragma unroll
                for (int r = 0; r < RANK; r++)
                    wv[r] = wp[r * (INDIM / 4) + j];   // uniform LDG.128 broadcast
                #pragma unroll
                for (int r = 0; r < RANK; r++) {
                    fma2(a01[r], xv.x, wv[r].x);
                    fma2(a23[r], xv.y, wv[r].y);
                }
            }
            cbuf = (cbuf + 1 == NBUF) ? 0 : cbuf + 1;
            if (cbuf == 0) cph ^= 1;
        }

        // cross-warp reduce: 8 warp partials per (row, r)
        {
            float v[RANK];
            #pragma unroll
            for (int r = 0; r < RANK; r++) {
                float2 p = unpk(a01[r]); float2 qq = unpk(a23[r]);
                v[r] = (p.x + p.y) + (qq.x + qq.y);
            }
            float4* dst = (float4*)(sm + S_RED + wid * (TROWS * RANK) + lane * RANK);
            dst[0] = make_float4(v[0], v[1], v[2], v[3]);
            dst[1] = make_float4(v[4], v[5], v[6], v[7]);
        }
        __syncthreads();
        {
            float s = 0.0f;     // all 256 threads: tid = row*8 + r
            #pragma unroll
            for (int w2 = 0; w2 < 8; w2++)
                s += sm[S_RED + w2 * (TROWS * RANK) + tid];
            sm[S_INT + tid] = s;
        }
        __syncthreads();

        // epilogue: thread owns 4 float4 col groups; W_B from L2/L1 (pre-scaled)
        {
            size_t outbase = (size_t)t * TROWS * OUTDIM;
            const float4* gWB4 = (const float4*)g_WBt;
            #pragma unroll
            for (int og = 0; og < 4; og++) {
                int g = tid + og * NTHR;
                unsigned long long wb01[RANK], wb23[RANK];
                #pragma unroll
                for (int r = 0; r < RANK; r++) {
                    float4 w = __ldg(gWB4 + r * (OUTDIM / 4) + g);
                    wb01[r] = pkab(w.x, w.y);
                    wb23[r] = pkab(w.z, w.w);
                }
                #pragma unroll 4
                for (int m = 0; m < TROWS; m++) {
                    const float4* ip = (const float4*)(sm + S_INT) + m * 2;
                    float4 s0 = ip[0], s1 = ip[1];   // broadcast LDS
                    float sv[RANK] = { s0.x, s0.y, s0.z, s0.w,
                                       s1.x, s1.y, s1.z, s1.w };
                    unsigned long long o01 = 0ull, o23 = 0ull;
                    #pragma unroll
                    for (int r = 0; r < RANK; r++) {
                        unsigned long long s2 = pk2(sv[r]);
                        fma2(o01, s2, wb01[r]);
                        fma2(o23, s2, wb23[r]);
                    }
                    ulonglong2 ov; ov.x = o01; ov.y = o23;
                    *(ulonglong2*)(out + outbase + (size_t)m * OUTDIM + g * 4) = ov;
                }
            }
        }
    }
}

extern "C" void kernel_launch(void* const* d_in, const int* in_sizes, int n_in,
                              void* d_out, int out_size) {
    const float* x        = (const float*)d_in[0];
    const int*   codes_A  = (const int*)d_in[1];
    const float* absmax_A = (const float*)d_in[2];
    const int*   codes_B  = (const int*)d_in[3];
    const float* absmax_B = (const float*)d_in[4];
    float*       out      = (float*)d_out;
    (void)in_sizes; (void)n_in; (void)out_size;

    // single dequant launch covering both A (32768) and B (32768)
    dequant_kernel<<<(2 * RANK * INDIM + 255) / 256, 256>>>(
        codes_A, absmax_A, codes_B, absmax_B);

    int dev = 0, nsm = 148;
    cudaGetDevice(&dev);
    cudaDeviceGetAttribute(&nsm, cudaDevAttrMultiProcessorCount, dev);
    int grid = 2 * nsm;   // 2 CTAs/SM; 256 working CTAs finish in one wave

    cudaFuncSetAttribute(qlora_kernel,
                         cudaFuncAttributeMaxDynamicSharedMemorySize, SMEM_BYTES);
    qlora_kernel<<<grid, NTHR, SMEM_BYTES>>>(x, out);
}